// round 15
// baseline (speedup 1.0000x reference)
#include <cuda_runtime.h>
#include <cuda_fp16.h>
#include <cstdint>
#include <cstddef>

#define N_NODES 50000
#define N_EDGES 500000
#define H 128
#define H3 384
#define SCAN_B 256
#define N_SBLK ((N_NODES + SCAN_B - 1) / SCAN_B)   // 196

// ---------------- scratch (static device allocations, allowed) --------------
// packed per-node gather row: [es(128h) | er(128h) | q0(3*128h)] = 640 halves
// q0[a,k] = ev[k] * v[node,a,k]
#define PACK_H2 320
__device__ __half2 g_pack[(size_t)N_NODES * PACK_H2];   // 64 MB
// g_state: [0,N) degree counts | [N,2N) fill cursors | [2N,2N+SBLK) scan states
__device__ int    g_state[2 * N_NODES + N_SBLK];
__device__ int    g_start[N_NODES + 1];
__device__ int    g_bsrc [N_EDGES];
__device__ float4 g_bdat [N_EDGES];                      // {d, dir0, dir1, dir2}

// ---------------------------------------------------------------------------
// fp16 mma helpers (m16n8k16, fp32 accumulate) + ldmatrix
// ---------------------------------------------------------------------------
__device__ __forceinline__ void mma_f16(float c[4],
                                        uint32_t a0, uint32_t a1,
                                        uint32_t a2, uint32_t a3,
                                        uint32_t b0, uint32_t b1) {
    asm volatile(
        "mma.sync.aligned.m16n8k16.row.col.f32.f16.f16.f32 "
        "{%0,%1,%2,%3}, {%4,%5,%6,%7}, {%8,%9}, {%0,%1,%2,%3};"
        : "+f"(c[0]), "+f"(c[1]), "+f"(c[2]), "+f"(c[3])
        : "r"(a0), "r"(a1), "r"(a2), "r"(a3), "r"(b0), "r"(b1));
}

__device__ __forceinline__ void ldsm_x4(uint32_t r[4], uint32_t addr) {
    asm volatile("ldmatrix.sync.aligned.m8n8.x4.shared.b16 {%0,%1,%2,%3}, [%4];"
                 : "=r"(r[0]), "=r"(r[1]), "=r"(r[2]), "=r"(r[3]) : "r"(addr));
}

__device__ __forceinline__ void ldsm_x2t(uint32_t& b0, uint32_t& b1,
                                         uint32_t addr) {
    asm volatile("ldmatrix.sync.aligned.m8n8.x2.trans.shared.b16 {%0,%1}, [%2];"
                 : "=r"(b0), "=r"(b1) : "r"(addr));
}

// ---------------------------------------------------------------------------
// Kernel 1: s_exp = tanh(s @ W1 + b1) @ W2 + b2, fused epilogue packs
//   chunk0 (ev) -> q0[a] = ev * v[row,a,:]   chunk1 -> es   chunk2 -> er
// ---------------------------------------------------------------------------
#define BM 128
#define SWH 136
#define SMEM_EMBED_BYTES (2 * 128 * SWH * 2)

__device__ __forceinline__ void st_half4(__half* base, int row, int c4,
                                         float4 v) {
    __half2 p0 = __floats2half2_rn(v.x, v.y);
    __half2 p1 = __floats2half2_rn(v.z, v.w);
    uint2 u;
    u.x = *reinterpret_cast<uint32_t*>(&p0);
    u.y = *reinterpret_cast<uint32_t*>(&p1);
    *reinterpret_cast<uint2*>(base + row * SWH + c4) = u;
}

__device__ __forceinline__ void compute_mma16(float acc[4][4][4],
                                              uint32_t sA32, uint32_t sW32,
                                              int wm, int wn, int lane) {
    const int quad = lane >> 3;
    const int lr   = lane & 7;
    const int bk   = lane & 15;
#pragma unroll
    for (int ks = 0; ks < 8; ks++) {
        uint32_t a[4][4];
#pragma unroll
        for (int mt = 0; mt < 4; mt++) {
            int arow = wm * 64 + mt * 16 + (quad & 1) * 8 + lr;
            int acol = ks * 16 + (quad >> 1) * 8;
            ldsm_x4(a[mt], sA32 + (arow * SWH + acol) * 2);
        }
#pragma unroll
        for (int nt = 0; nt < 4; nt++) {
            int brow = ks * 16 + bk;
            int bcol = wn * 32 + nt * 8;
            uint32_t b0, b1;
            ldsm_x2t(b0, b1, sW32 + (brow * SWH + bcol) * 2);
#pragma unroll
            for (int mt = 0; mt < 4; mt++)
                mma_f16(acc[mt][nt], a[mt][0], a[mt][1], a[mt][2], a[mt][3],
                        b0, b1);
        }
    }
}

__device__ __forceinline__ void pack_store(int row, int chunk, int col,
                                           float r0, float r1,
                                           const float* __restrict__ v) {
    if (row >= N_NODES) return;
    __half2* pr = g_pack + (size_t)row * PACK_H2;
    if (chunk == 0) {
#pragma unroll
        for (int a = 0; a < 3; a++) {
            float2 vv = *(const float2*)(v + (size_t)row * H3 + a * H + col);
            pr[128 + a * 64 + (col >> 1)] =
                __floats2half2_rn(r0 * vv.x, r1 * vv.y);
        }
    } else if (chunk == 1) {
        pr[(col - 128) >> 1] = __floats2half2_rn(r0, r1);        // es
    } else {
        pr[64 + ((col - 256) >> 1)] = __floats2half2_rn(r0, r1); // er
    }
}

__global__ __launch_bounds__(256) void embed_kernel(
    const float* __restrict__ s,
    const float* __restrict__ v,
    const float* __restrict__ W1, const float* __restrict__ b1,
    const float* __restrict__ W2, const float* __restrict__ b2)
{
    extern __shared__ __half smem_h[];
    __half* sA = smem_h;
    __half* sW = smem_h + 128 * SWH;

    const uint32_t sA32 = (uint32_t)__cvta_generic_to_shared(sA);
    const uint32_t sW32 = (uint32_t)__cvta_generic_to_shared(sW);

    const int t    = threadIdx.x;
    const int r0   = blockIdx.x * BM;
    const int wid  = t >> 5, lane = t & 31;
    const int wm   = wid & 1, wn = wid >> 1;
    const int gid  = lane >> 2, tig = lane & 3;

#pragma unroll
    for (int i = 0; i < 16; i++) {
        int idx4 = t + i * 256;
        int row  = idx4 >> 5;
        int c4   = (idx4 & 31) * 4;
        float4 val = make_float4(0.f, 0.f, 0.f, 0.f);
        if (r0 + row < N_NODES)
            val = *(const float4*)(s + (size_t)(r0 + row) * H + c4);
        st_half4(sA, row, c4, val);
    }
#pragma unroll
    for (int i = 0; i < 16; i++) {
        int idx4 = t + i * 256;
        int row  = idx4 >> 5;
        int c4   = (idx4 & 31) * 4;
        st_half4(sW, row, c4, *(const float4*)(W1 + (size_t)row * H + c4));
    }
    __syncthreads();

    float acc[4][4][4];
#pragma unroll
    for (int mt = 0; mt < 4; mt++)
#pragma unroll
        for (int nt = 0; nt < 4; nt++)
#pragma unroll
            for (int i = 0; i < 4; i++) acc[mt][nt][i] = 0.f;

    compute_mma16(acc, sA32, sW32, wm, wn, lane);
    __syncthreads();

#pragma unroll
    for (int mt = 0; mt < 4; mt++) {
        int row = wm * 64 + mt * 16 + gid;
#pragma unroll
        for (int nt = 0; nt < 4; nt++) {
            int col = wn * 32 + nt * 8 + tig * 2;
            float ba = __ldg(b1 + col), bb = __ldg(b1 + col + 1);
            *(half2*)(sA + row * SWH + col) =
                __floats2half2_rn(tanhf(acc[mt][nt][0] + ba),
                                  tanhf(acc[mt][nt][1] + bb));
            *(half2*)(sA + (row + 8) * SWH + col) =
                __floats2half2_rn(tanhf(acc[mt][nt][2] + ba),
                                  tanhf(acc[mt][nt][3] + bb));
        }
    }

    for (int chunk = 0; chunk < 3; chunk++) {
        __syncthreads();
#pragma unroll
        for (int i = 0; i < 16; i++) {
            int idx4 = t + i * 256;
            int row  = idx4 >> 5;
            int c4   = (idx4 & 31) * 4;
            st_half4(sW, row, c4,
                     *(const float4*)(W2 + (size_t)row * H3 + chunk * 128 + c4));
        }
        __syncthreads();

        float acc2[4][4][4];
#pragma unroll
        for (int mt = 0; mt < 4; mt++)
#pragma unroll
            for (int nt = 0; nt < 4; nt++)
#pragma unroll
                for (int i = 0; i < 4; i++) acc2[mt][nt][i] = 0.f;

        compute_mma16(acc2, sA32, sW32, wm, wn, lane);

#pragma unroll
        for (int mt = 0; mt < 4; mt++) {
            int rl = wm * 64 + mt * 16 + gid;
#pragma unroll
            for (int nt = 0; nt < 4; nt++) {
                int col = chunk * 128 + wn * 32 + nt * 8 + tig * 2;
                float ba = __ldg(b2 + col), bb = __ldg(b2 + col + 1);
                int lcol = col - chunk * 128;
                pack_store(r0 + rl, chunk, chunk ? col : lcol,
                           acc2[mt][nt][0] + ba, acc2[mt][nt][1] + bb, v);
                pack_store(r0 + rl + 8, chunk, chunk ? col : lcol,
                           acc2[mt][nt][2] + ba, acc2[mt][nt][3] + bb, v);
            }
        }
    }
}

// ---------------------------------------------------------------------------
// CSR build: histogram -> single-kernel lookback scan -> bucket fill
// ---------------------------------------------------------------------------
__global__ __launch_bounds__(256) void hist_kernel(const int* __restrict__ ei) {
    int i = blockIdx.x * 256 + threadIdx.x;
    if (i < N_EDGES) atomicAdd(&g_state[__ldg(ei + N_EDGES + i)], 1);
}

__global__ __launch_bounds__(SCAN_B) void scan_lb_kernel() {
    __shared__ int tmp[SCAN_B];
    __shared__ int s_prefix;
    const int b = blockIdx.x;
    const int t = threadIdx.x;
    const int idx = b * SCAN_B + t;
    int* states = g_state + 2 * N_NODES;

    int v = (idx < N_NODES) ? g_state[idx] : 0;
    tmp[t] = v;
    __syncthreads();
#pragma unroll
    for (int off = 1; off < SCAN_B; off <<= 1) {
        int u = (t >= off) ? tmp[t - off] : 0;
        __syncthreads();
        tmp[t] += u;
        __syncthreads();
    }
    const int incl = tmp[t];
    const int total = tmp[SCAN_B - 1];

    if (t == 0) {
        if (b == 0) {
            __threadfence();
            atomicExch(&states[0], (total << 2) | 2);   // PREFIX
            s_prefix = 0;
        } else {
            __threadfence();
            atomicExch(&states[b], (total << 2) | 1);   // AGGREGATE
            int run = 0;
            int i = b - 1;
            while (true) {
                int st;
                do { st = atomicAdd(&states[i], 0); } while ((st & 3) == 0);
                run += (st >> 2);
                if ((st & 3) == 2) break;
                --i;
            }
            s_prefix = run;
            __threadfence();
            atomicExch(&states[b], ((run + total) << 2) | 2);
        }
    }
    __syncthreads();

    if (idx < N_NODES) g_start[idx] = s_prefix + incl - v;   // exclusive
    if (idx == 0)      g_start[N_NODES] = N_EDGES;
}

__global__ __launch_bounds__(256) void fill_kernel(
    const int* __restrict__ ei,
    const float* __restrict__ dij,
    const float* __restrict__ dir)
{
    int e = blockIdx.x * 256 + threadIdx.x;
    if (e >= N_EDGES) return;
    int dst = __ldg(ei + N_EDGES + e);
    int pos = g_start[dst] + atomicAdd(&g_state[N_NODES + dst], 1);
    g_bsrc[pos] = __ldg(ei + e);
    g_bdat[pos] = make_float4(__ldg(dij + e), __ldg(dir + 3 * e),
                              __ldg(dir + 3 * e + 1), __ldg(dir + 3 * e + 2));
}

// ---------------------------------------------------------------------------
// Kernel 2: gather + finalize. 128-thread block = 2 nodes x 64 threads.
// 5 packed gathers per edge: es, er, q0[0..2].
// ---------------------------------------------------------------------------
__global__ __launch_bounds__(128) void gather_kernel(
    const float* __restrict__ v,
    const float* __restrict__ s,
    const float* __restrict__ Wd,
    const float* __restrict__ bd,
    float* __restrict__ out)
{
    const int t    = threadIdx.x;
    const int node = blockIdx.x * 2 + (t >> 6);
    const int c    = t & 63;

    const int beg = g_start[node];
    const int end = g_start[node + 1];

    const float2 wv = *(const float2*)(Wd + 2 * c);
    const float2 bv = *(const float2*)(bd + 2 * c);
    const float2 ws = *(const float2*)(Wd + 128 + 2 * c);
    const float2 bs = *(const float2*)(bd + 128 + 2 * c);
    const float2 wr = *(const float2*)(Wd + 256 + 2 * c);
    const float2 br = *(const float2*)(bd + 256 + 2 * c);

    float2 accs = make_float2(0.f, 0.f);
    float2 a0 = accs, a1 = accs, a2 = accs;

#pragma unroll 4
    for (int j = beg; j < end; j++) {
        const int src = __ldg(g_bsrc + j);
        const float4 ed = __ldg(g_bdat + j);    // {d, d0, d1, d2}

        const __half2* pr = g_pack + (size_t)src * PACK_H2;
        const float2 es = __half22float2(__ldg(pr + c));
        const float2 er = __half22float2(__ldg(pr + 64 + c));
        const float2 q0 = __half22float2(__ldg(pr + 128 + c));
        const float2 q1 = __half22float2(__ldg(pr + 192 + c));
        const float2 q2 = __half22float2(__ldg(pr + 256 + c));

        const float gqx = fmaf(ed.x, wv.x, bv.x);
        const float gqy = fmaf(ed.x, wv.y, bv.y);
        const float grx = er.x * fmaf(ed.x, wr.x, br.x);
        const float gry = er.y * fmaf(ed.x, wr.y, br.y);

        accs.x = fmaf(es.x, fmaf(ed.x, ws.x, bs.x), accs.x);
        accs.y = fmaf(es.y, fmaf(ed.x, ws.y, bs.y), accs.y);

        a0.x = fmaf(grx, ed.y, fmaf(gqx, q0.x, a0.x));
        a0.y = fmaf(gry, ed.y, fmaf(gqy, q0.y, a0.y));
        a1.x = fmaf(grx, ed.z, fmaf(gqx, q1.x, a1.x));
        a1.y = fmaf(gry, ed.z, fmaf(gqy, q1.y, a1.y));
        a2.x = fmaf(grx, ed.w, fmaf(gqx, q2.x, a2.x));
        a2.y = fmaf(gry, ed.w, fmaf(gqy, q2.y, a2.y));
    }

    const float inv = 1.0f / fmaxf((float)(end - beg), 1.0f);

    const size_t vb = (size_t)node * H3;
    float2 o;
    float2 x0 = *(const float2*)(v + vb + 2 * c);
    o = make_float2(fmaf(a0.x, inv, x0.x), fmaf(a0.y, inv, x0.y));
    *(float2*)(out + vb + 2 * c) = o;
    float2 x1 = *(const float2*)(v + vb + 128 + 2 * c);
    o = make_float2(fmaf(a1.x, inv, x1.x), fmaf(a1.y, inv, x1.y));
    *(float2*)(out + vb + 128 + 2 * c) = o;
    float2 x2 = *(const float2*)(v + vb + 256 + 2 * c);
    o = make_float2(fmaf(a2.x, inv, x2.x), fmaf(a2.y, inv, x2.y));
    *(float2*)(out + vb + 256 + 2 * c) = o;

    float2 xs = *(const float2*)(s + (size_t)node * H + 2 * c);
    o = make_float2(fmaf(accs.x, inv, xs.x), fmaf(accs.y, inv, xs.y));
    *(float2*)(out + (size_t)N_NODES * H3 + (size_t)node * H + 2 * c) = o;
}

// ---------------------------------------------------------------------------
// Launch (submission order fixes ncu -s 5 onto gather):
//   0 memset(sC) 1 hist(sC) 2 scan(sC) 3 fill(sC) 4 embed(s0) 5 gather(s0)
// ---------------------------------------------------------------------------
extern "C" void kernel_launch(void* const* d_in, const int* in_sizes, int n_in,
                              void* d_out, int out_size) {
    const float* v   = (const float*)d_in[0];
    const float* s   = (const float*)d_in[1];
    const int*   ei  = (const int*)  d_in[2];
    const float* dij = (const float*)d_in[3];
    const float* dir = (const float*)d_in[4];
    const float* W1  = (const float*)d_in[5];
    const float* b1  = (const float*)d_in[6];
    const float* W2  = (const float*)d_in[7];
    const float* b2  = (const float*)d_in[8];
    const float* Wd  = (const float*)d_in[9];
    const float* bd  = (const float*)d_in[10];
    float* out = (float*)d_out;

    static cudaStream_t sC = nullptr;
    static cudaEvent_t  eFork = nullptr, eJoinC = nullptr;
    if (sC == nullptr) {
        cudaStreamCreateWithFlags(&sC, cudaStreamNonBlocking);
        cudaEventCreateWithFlags(&eFork,  cudaEventDisableTiming);
        cudaEventCreateWithFlags(&eJoinC, cudaEventDisableTiming);
        cudaFuncSetAttribute(embed_kernel,
                             cudaFuncAttributeMaxDynamicSharedMemorySize,
                             SMEM_EMBED_BYTES);
    }

    void* pstate;
    cudaGetSymbolAddress(&pstate, g_state);

    cudaEventRecord(eFork, 0);
    cudaStreamWaitEvent(sC, eFork, 0);

    // chain C: CSR build
    cudaMemsetAsync(pstate, 0, sizeof(int) * (2 * N_NODES + N_SBLK), sC);
    hist_kernel<<<(N_EDGES + 255) / 256, 256, 0, sC>>>(ei);
    scan_lb_kernel<<<N_SBLK, SCAN_B, 0, sC>>>();
    fill_kernel<<<(N_EDGES + 255) / 256, 256, 0, sC>>>(ei, dij, dir);

    // chain A: embed MLP + pack epilogue
    embed_kernel<<<(N_NODES + BM - 1) / BM, 256, SMEM_EMBED_BYTES>>>(
        s, v, W1, b1, W2, b2);

    cudaEventRecord(eJoinC, sC);
    cudaStreamWaitEvent(0, eJoinC, 0);

    gather_kernel<<<(N_NODES + 1) / 2, 128>>>(v, s, Wd, bd, out);
}

// round 16
// speedup vs baseline: 1.0699x; 1.0699x over previous
#include <cuda_runtime.h>
#include <cuda_fp16.h>
#include <cstdint>
#include <cstddef>

#define N_NODES 50000
#define N_EDGES 500000
#define H 128
#define H3 384
#define SCAN_B 256
#define N_SBLK ((N_NODES + SCAN_B - 1) / SCAN_B)   // 196

// ---------------- scratch (static device allocations, allowed) --------------
// packed per-node gather row: [es(128h) | er(128h) | q0(3*128h)] = 640 halves
// q0[a,k] = ev[k] * v[node,a,k]
#define PACK_H2 320
__device__ __half2 g_pack[(size_t)N_NODES * PACK_H2];   // 64 MB
// g_state: [0,N) degree counts | [N,2N) fill cursors | [2N,2N+SBLK) scan states
__device__ int    g_state[2 * N_NODES + N_SBLK];
__device__ int    g_start[N_NODES + 1];
__device__ int    g_bsrc [N_EDGES];
__device__ float4 g_bdat [N_EDGES];                      // {d, dir0, dir1, dir2}

// ---------------------------------------------------------------------------
// fp16 mma helpers (m16n8k16, fp32 accumulate) + ldmatrix
// ---------------------------------------------------------------------------
__device__ __forceinline__ void mma_f16(float c[4],
                                        uint32_t a0, uint32_t a1,
                                        uint32_t a2, uint32_t a3,
                                        uint32_t b0, uint32_t b1) {
    asm volatile(
        "mma.sync.aligned.m16n8k16.row.col.f32.f16.f16.f32 "
        "{%0,%1,%2,%3}, {%4,%5,%6,%7}, {%8,%9}, {%0,%1,%2,%3};"
        : "+f"(c[0]), "+f"(c[1]), "+f"(c[2]), "+f"(c[3])
        : "r"(a0), "r"(a1), "r"(a2), "r"(a3), "r"(b0), "r"(b1));
}

__device__ __forceinline__ void ldsm_x4(uint32_t r[4], uint32_t addr) {
    asm volatile("ldmatrix.sync.aligned.m8n8.x4.shared.b16 {%0,%1,%2,%3}, [%4];"
                 : "=r"(r[0]), "=r"(r[1]), "=r"(r[2]), "=r"(r[3]) : "r"(addr));
}

__device__ __forceinline__ void ldsm_x2t(uint32_t& b0, uint32_t& b1,
                                         uint32_t addr) {
    asm volatile("ldmatrix.sync.aligned.m8n8.x2.trans.shared.b16 {%0,%1}, [%2];"
                 : "=r"(b0), "=r"(b1) : "r"(addr));
}

// ---------------------------------------------------------------------------
// Kernel 1: s_exp = tanh(s @ W1 + b1) @ W2 + b2, fused epilogue packs
//   chunk0 (ev) -> q0[a] = ev * v[row,a,:]   chunk1 -> es   chunk2 -> er
// __launch_bounds__(256, 2): cap regs at 128/thread so 2 blocks/SM resident.
// ---------------------------------------------------------------------------
#define BM 128
#define SWH 136
#define SMEM_EMBED_BYTES (2 * 128 * SWH * 2)

__device__ __forceinline__ void st_half4(__half* base, int row, int c4,
                                         float4 v) {
    __half2 p0 = __floats2half2_rn(v.x, v.y);
    __half2 p1 = __floats2half2_rn(v.z, v.w);
    uint2 u;
    u.x = *reinterpret_cast<uint32_t*>(&p0);
    u.y = *reinterpret_cast<uint32_t*>(&p1);
    *reinterpret_cast<uint2*>(base + row * SWH + c4) = u;
}

__device__ __forceinline__ void compute_mma16(float acc[4][4][4],
                                              uint32_t sA32, uint32_t sW32,
                                              int wm, int wn, int lane) {
    const int quad = lane >> 3;
    const int lr   = lane & 7;
    const int bk   = lane & 15;
#pragma unroll
    for (int ks = 0; ks < 8; ks++) {
        uint32_t a[4][4];
#pragma unroll
        for (int mt = 0; mt < 4; mt++) {
            int arow = wm * 64 + mt * 16 + (quad & 1) * 8 + lr;
            int acol = ks * 16 + (quad >> 1) * 8;
            ldsm_x4(a[mt], sA32 + (arow * SWH + acol) * 2);
        }
#pragma unroll
        for (int nt = 0; nt < 4; nt++) {
            int brow = ks * 16 + bk;
            int bcol = wn * 32 + nt * 8;
            uint32_t b0, b1;
            ldsm_x2t(b0, b1, sW32 + (brow * SWH + bcol) * 2);
#pragma unroll
            for (int mt = 0; mt < 4; mt++)
                mma_f16(acc[mt][nt], a[mt][0], a[mt][1], a[mt][2], a[mt][3],
                        b0, b1);
        }
    }
}

__device__ __forceinline__ void pack_store(int row, int chunk, int col,
                                           float r0, float r1,
                                           const float* __restrict__ v) {
    if (row >= N_NODES) return;
    __half2* pr = g_pack + (size_t)row * PACK_H2;
    if (chunk == 0) {
#pragma unroll
        for (int a = 0; a < 3; a++) {
            float2 vv = *(const float2*)(v + (size_t)row * H3 + a * H + col);
            pr[128 + a * 64 + (col >> 1)] =
                __floats2half2_rn(r0 * vv.x, r1 * vv.y);
        }
    } else if (chunk == 1) {
        pr[(col - 128) >> 1] = __floats2half2_rn(r0, r1);        // es
    } else {
        pr[64 + ((col - 256) >> 1)] = __floats2half2_rn(r0, r1); // er
    }
}

__global__ __launch_bounds__(256, 2) void embed_kernel(
    const float* __restrict__ s,
    const float* __restrict__ v,
    const float* __restrict__ W1, const float* __restrict__ b1,
    const float* __restrict__ W2, const float* __restrict__ b2)
{
    extern __shared__ __half smem_h[];
    __half* sA = smem_h;
    __half* sW = smem_h + 128 * SWH;

    const uint32_t sA32 = (uint32_t)__cvta_generic_to_shared(sA);
    const uint32_t sW32 = (uint32_t)__cvta_generic_to_shared(sW);

    const int t    = threadIdx.x;
    const int r0   = blockIdx.x * BM;
    const int wid  = t >> 5, lane = t & 31;
    const int wm   = wid & 1, wn = wid >> 1;
    const int gid  = lane >> 2, tig = lane & 3;

#pragma unroll
    for (int i = 0; i < 16; i++) {
        int idx4 = t + i * 256;
        int row  = idx4 >> 5;
        int c4   = (idx4 & 31) * 4;
        float4 val = make_float4(0.f, 0.f, 0.f, 0.f);
        if (r0 + row < N_NODES)
            val = *(const float4*)(s + (size_t)(r0 + row) * H + c4);
        st_half4(sA, row, c4, val);
    }
#pragma unroll
    for (int i = 0; i < 16; i++) {
        int idx4 = t + i * 256;
        int row  = idx4 >> 5;
        int c4   = (idx4 & 31) * 4;
        st_half4(sW, row, c4, *(const float4*)(W1 + (size_t)row * H + c4));
    }
    __syncthreads();

    float acc[4][4][4];
#pragma unroll
    for (int mt = 0; mt < 4; mt++)
#pragma unroll
        for (int nt = 0; nt < 4; nt++)
#pragma unroll
            for (int i = 0; i < 4; i++) acc[mt][nt][i] = 0.f;

    compute_mma16(acc, sA32, sW32, wm, wn, lane);
    __syncthreads();

#pragma unroll
    for (int mt = 0; mt < 4; mt++) {
        int row = wm * 64 + mt * 16 + gid;
#pragma unroll
        for (int nt = 0; nt < 4; nt++) {
            int col = wn * 32 + nt * 8 + tig * 2;
            float ba = __ldg(b1 + col), bb = __ldg(b1 + col + 1);
            *(half2*)(sA + row * SWH + col) =
                __floats2half2_rn(tanhf(acc[mt][nt][0] + ba),
                                  tanhf(acc[mt][nt][1] + bb));
            *(half2*)(sA + (row + 8) * SWH + col) =
                __floats2half2_rn(tanhf(acc[mt][nt][2] + ba),
                                  tanhf(acc[mt][nt][3] + bb));
        }
    }

    for (int chunk = 0; chunk < 3; chunk++) {
        __syncthreads();
#pragma unroll
        for (int i = 0; i < 16; i++) {
            int idx4 = t + i * 256;
            int row  = idx4 >> 5;
            int c4   = (idx4 & 31) * 4;
            st_half4(sW, row, c4,
                     *(const float4*)(W2 + (size_t)row * H3 + chunk * 128 + c4));
        }
        __syncthreads();

        float acc2[4][4][4];
#pragma unroll
        for (int mt = 0; mt < 4; mt++)
#pragma unroll
            for (int nt = 0; nt < 4; nt++)
#pragma unroll
                for (int i = 0; i < 4; i++) acc2[mt][nt][i] = 0.f;

        compute_mma16(acc2, sA32, sW32, wm, wn, lane);

#pragma unroll
        for (int mt = 0; mt < 4; mt++) {
            int rl = wm * 64 + mt * 16 + gid;
#pragma unroll
            for (int nt = 0; nt < 4; nt++) {
                int col = chunk * 128 + wn * 32 + nt * 8 + tig * 2;
                float ba = __ldg(b2 + col), bb = __ldg(b2 + col + 1);
                int lcol = col - chunk * 128;
                pack_store(r0 + rl, chunk, chunk ? col : lcol,
                           acc2[mt][nt][0] + ba, acc2[mt][nt][1] + bb, v);
                pack_store(r0 + rl + 8, chunk, chunk ? col : lcol,
                           acc2[mt][nt][2] + ba, acc2[mt][nt][3] + bb, v);
            }
        }
    }
}

// ---------------------------------------------------------------------------
// CSR build: histogram -> single-kernel lookback scan -> bucket fill
// ---------------------------------------------------------------------------
__global__ __launch_bounds__(256) void hist_kernel(const int* __restrict__ ei) {
    int i = blockIdx.x * 256 + threadIdx.x;
    if (i < N_EDGES) atomicAdd(&g_state[__ldg(ei + N_EDGES + i)], 1);
}

__global__ __launch_bounds__(SCAN_B) void scan_lb_kernel() {
    __shared__ int tmp[SCAN_B];
    __shared__ int s_prefix;
    const int b = blockIdx.x;
    const int t = threadIdx.x;
    const int idx = b * SCAN_B + t;
    int* states = g_state + 2 * N_NODES;

    int v = (idx < N_NODES) ? g_state[idx] : 0;
    tmp[t] = v;
    __syncthreads();
#pragma unroll
    for (int off = 1; off < SCAN_B; off <<= 1) {
        int u = (t >= off) ? tmp[t - off] : 0;
        __syncthreads();
        tmp[t] += u;
        __syncthreads();
    }
    const int incl = tmp[t];
    const int total = tmp[SCAN_B - 1];

    if (t == 0) {
        if (b == 0) {
            __threadfence();
            atomicExch(&states[0], (total << 2) | 2);   // PREFIX
            s_prefix = 0;
        } else {
            __threadfence();
            atomicExch(&states[b], (total << 2) | 1);   // AGGREGATE
            int run = 0;
            int i = b - 1;
            while (true) {
                int st;
                do { st = atomicAdd(&states[i], 0); } while ((st & 3) == 0);
                run += (st >> 2);
                if ((st & 3) == 2) break;
                --i;
            }
            s_prefix = run;
            __threadfence();
            atomicExch(&states[b], ((run + total) << 2) | 2);
        }
    }
    __syncthreads();

    if (idx < N_NODES) g_start[idx] = s_prefix + incl - v;   // exclusive
    if (idx == 0)      g_start[N_NODES] = N_EDGES;
}

__global__ __launch_bounds__(256) void fill_kernel(
    const int* __restrict__ ei,
    const float* __restrict__ dij,
    const float* __restrict__ dir)
{
    int e = blockIdx.x * 256 + threadIdx.x;
    if (e >= N_EDGES) return;
    int dst = __ldg(ei + N_EDGES + e);
    int pos = g_start[dst] + atomicAdd(&g_state[N_NODES + dst], 1);
    g_bsrc[pos] = __ldg(ei + e);
    g_bdat[pos] = make_float4(__ldg(dij + e), __ldg(dir + 3 * e),
                              __ldg(dir + 3 * e + 1), __ldg(dir + 3 * e + 2));
}

// ---------------------------------------------------------------------------
// Kernel 2: gather + finalize. 128-thread block = 2 nodes x 64 threads.
// 5 packed gathers per edge: es, er, q0[0..2].
// ---------------------------------------------------------------------------
__global__ __launch_bounds__(128) void gather_kernel(
    const float* __restrict__ v,
    const float* __restrict__ s,
    const float* __restrict__ Wd,
    const float* __restrict__ bd,
    float* __restrict__ out)
{
    const int t    = threadIdx.x;
    const int node = blockIdx.x * 2 + (t >> 6);
    const int c    = t & 63;

    const int beg = g_start[node];
    const int end = g_start[node + 1];

    const float2 wv = *(const float2*)(Wd + 2 * c);
    const float2 bv = *(const float2*)(bd + 2 * c);
    const float2 ws = *(const float2*)(Wd + 128 + 2 * c);
    const float2 bs = *(const float2*)(bd + 128 + 2 * c);
    const float2 wr = *(const float2*)(Wd + 256 + 2 * c);
    const float2 br = *(const float2*)(bd + 256 + 2 * c);

    float2 accs = make_float2(0.f, 0.f);
    float2 a0 = accs, a1 = accs, a2 = accs;

#pragma unroll 4
    for (int j = beg; j < end; j++) {
        const int src = __ldg(g_bsrc + j);
        const float4 ed = __ldg(g_bdat + j);    // {d, d0, d1, d2}

        const __half2* pr = g_pack + (size_t)src * PACK_H2;
        const float2 es = __half22float2(__ldg(pr + c));
        const float2 er = __half22float2(__ldg(pr + 64 + c));
        const float2 q0 = __half22float2(__ldg(pr + 128 + c));
        const float2 q1 = __half22float2(__ldg(pr + 192 + c));
        const float2 q2 = __half22float2(__ldg(pr + 256 + c));

        const float gqx = fmaf(ed.x, wv.x, bv.x);
        const float gqy = fmaf(ed.x, wv.y, bv.y);
        const float grx = er.x * fmaf(ed.x, wr.x, br.x);
        const float gry = er.y * fmaf(ed.x, wr.y, br.y);

        accs.x = fmaf(es.x, fmaf(ed.x, ws.x, bs.x), accs.x);
        accs.y = fmaf(es.y, fmaf(ed.x, ws.y, bs.y), accs.y);

        a0.x = fmaf(grx, ed.y, fmaf(gqx, q0.x, a0.x));
        a0.y = fmaf(gry, ed.y, fmaf(gqy, q0.y, a0.y));
        a1.x = fmaf(grx, ed.z, fmaf(gqx, q1.x, a1.x));
        a1.y = fmaf(gry, ed.z, fmaf(gqy, q1.y, a1.y));
        a2.x = fmaf(grx, ed.w, fmaf(gqx, q2.x, a2.x));
        a2.y = fmaf(gry, ed.w, fmaf(gqy, q2.y, a2.y));
    }

    const float inv = 1.0f / fmaxf((float)(end - beg), 1.0f);

    const size_t vb = (size_t)node * H3;
    float2 o;
    float2 x0 = *(const float2*)(v + vb + 2 * c);
    o = make_float2(fmaf(a0.x, inv, x0.x), fmaf(a0.y, inv, x0.y));
    *(float2*)(out + vb + 2 * c) = o;
    float2 x1 = *(const float2*)(v + vb + 128 + 2 * c);
    o = make_float2(fmaf(a1.x, inv, x1.x), fmaf(a1.y, inv, x1.y));
    *(float2*)(out + vb + 128 + 2 * c) = o;
    float2 x2 = *(const float2*)(v + vb + 256 + 2 * c);
    o = make_float2(fmaf(a2.x, inv, x2.x), fmaf(a2.y, inv, x2.y));
    *(float2*)(out + vb + 256 + 2 * c) = o;

    float2 xs = *(const float2*)(s + (size_t)node * H + 2 * c);
    o = make_float2(fmaf(accs.x, inv, xs.x), fmaf(accs.y, inv, xs.y));
    *(float2*)(out + (size_t)N_NODES * H3 + (size_t)node * H + 2 * c) = o;
}

// ---------------------------------------------------------------------------
// Launch (submission order keeps ncu -s 5 on gather):
//   0 memset(sC) 1 hist(sC) 2 scan(sC) 3 fill(sC) 4 embed(s0) 5 gather(s0)
// ---------------------------------------------------------------------------
extern "C" void kernel_launch(void* const* d_in, const int* in_sizes, int n_in,
                              void* d_out, int out_size) {
    const float* v   = (const float*)d_in[0];
    const float* s   = (const float*)d_in[1];
    const int*   ei  = (const int*)  d_in[2];
    const float* dij = (const float*)d_in[3];
    const float* dir = (const float*)d_in[4];
    const float* W1  = (const float*)d_in[5];
    const float* b1  = (const float*)d_in[6];
    const float* W2  = (const float*)d_in[7];
    const float* b2  = (const float*)d_in[8];
    const float* Wd  = (const float*)d_in[9];
    const float* bd  = (const float*)d_in[10];
    float* out = (float*)d_out;

    static cudaStream_t sC = nullptr;
    static cudaEvent_t  eFork = nullptr, eJoinC = nullptr;
    if (sC == nullptr) {
        cudaStreamCreateWithFlags(&sC, cudaStreamNonBlocking);
        cudaEventCreateWithFlags(&eFork,  cudaEventDisableTiming);
        cudaEventCreateWithFlags(&eJoinC, cudaEventDisableTiming);
        cudaFuncSetAttribute(embed_kernel,
                             cudaFuncAttributeMaxDynamicSharedMemorySize,
                             SMEM_EMBED_BYTES);
    }

    void* pstate;
    cudaGetSymbolAddress(&pstate, g_state);

    cudaEventRecord(eFork, 0);
    cudaStreamWaitEvent(sC, eFork, 0);

    // chain C: CSR build
    cudaMemsetAsync(pstate, 0, sizeof(int) * (2 * N_NODES + N_SBLK), sC);
    hist_kernel<<<(N_EDGES + 255) / 256, 256, 0, sC>>>(ei);
    scan_lb_kernel<<<N_SBLK, SCAN_B, 0, sC>>>();
    fill_kernel<<<(N_EDGES + 255) / 256, 256, 0, sC>>>(ei, dij, dir);

    // chain A: embed MLP + pack epilogue
    embed_kernel<<<(N_NODES + BM - 1) / BM, 256, SMEM_EMBED_BYTES>>>(
        s, v, W1, b1, W2, b2);

    cudaEventRecord(eJoinC, sC);
    cudaStreamWaitEvent(0, eJoinC, 0);

    gather_kernel<<<(N_NODES + 1) / 2, 128>>>(v, s, Wd, bd, out);
}

// round 17
// speedup vs baseline: 1.1056x; 1.0334x over previous
#include <cuda_runtime.h>
#include <cuda_fp16.h>
#include <cstdint>
#include <cstddef>

#define N_NODES 50000
#define N_EDGES 500000
#define H 128
#define H3 384
#define SCAN_B 256
#define N_SBLK ((N_NODES + SCAN_B - 1) / SCAN_B)   // 196

// ---------------- scratch (static device allocations, allowed) --------------
// packed per-node gather row: [es(128h) | er(128h) | q0(3*128h)] = 640 halves
#define PACK_H2 320
__device__ __half2 g_pack[(size_t)N_NODES * PACK_H2];   // 64 MB
// g_state: [0,N) degree counts | [N,2N) fill cursors | [2N,2N+SBLK) scan states
__device__ int    g_state[2 * N_NODES + N_SBLK];
__device__ int    g_start[N_NODES + 1];
__device__ int    g_bsrc [N_EDGES];
__device__ float4 g_bdat [N_EDGES];                      // {d, dir0, dir1, dir2}

// ---------------------------------------------------------------------------
// fp16 mma helpers (m16n8k16, fp32 accumulate) + ldmatrix
// ---------------------------------------------------------------------------
__device__ __forceinline__ void mma_f16(float c[4],
                                        uint32_t a0, uint32_t a1,
                                        uint32_t a2, uint32_t a3,
                                        uint32_t b0, uint32_t b1) {
    asm volatile(
        "mma.sync.aligned.m16n8k16.row.col.f32.f16.f16.f32 "
        "{%0,%1,%2,%3}, {%4,%5,%6,%7}, {%8,%9}, {%0,%1,%2,%3};"
        : "+f"(c[0]), "+f"(c[1]), "+f"(c[2]), "+f"(c[3])
        : "r"(a0), "r"(a1), "r"(a2), "r"(a3), "r"(b0), "r"(b1));
}

__device__ __forceinline__ void ldsm_x4(uint32_t r[4], uint32_t addr) {
    asm volatile("ldmatrix.sync.aligned.m8n8.x4.shared.b16 {%0,%1,%2,%3}, [%4];"
                 : "=r"(r[0]), "=r"(r[1]), "=r"(r[2]), "=r"(r[3]) : "r"(addr));
}

__device__ __forceinline__ void ldsm_x2t(uint32_t& b0, uint32_t& b1,
                                         uint32_t addr) {
    asm volatile("ldmatrix.sync.aligned.m8n8.x2.trans.shared.b16 {%0,%1}, [%2];"
                 : "=r"(b0), "=r"(b1) : "r"(addr));
}

// ---------------------------------------------------------------------------
// Kernel 1: s_exp = tanh(s @ W1 + b1) @ W2 + b2, fused epilogue packs
//   chunk0 (ev) -> q0[a] = ev * v[row,a,:]   chunk1 -> es   chunk2 -> er
// BM=64: warp tile 32x32 (acc[2][4][4]=32 regs), 3 blocks/SM, 24 warps.
// ---------------------------------------------------------------------------
#define BM 64
#define SWH 136
#define SMEM_EMBED_BYTES ((BM + 128) * SWH * 2)

__device__ __forceinline__ void st_half4(__half* base, int row, int c4,
                                         float4 v) {
    __half2 p0 = __floats2half2_rn(v.x, v.y);
    __half2 p1 = __floats2half2_rn(v.z, v.w);
    uint2 u;
    u.x = *reinterpret_cast<uint32_t*>(&p0);
    u.y = *reinterpret_cast<uint32_t*>(&p1);
    *reinterpret_cast<uint2*>(base + row * SWH + c4) = u;
}

// acc[2][4][4]: warp covers rows wm*32 .. wm*32+31, cols wn*32 .. wn*32+31
__device__ __forceinline__ void compute_mma16(float acc[2][4][4],
                                              uint32_t sA32, uint32_t sW32,
                                              int wm, int wn, int lane) {
    const int quad = lane >> 3;
    const int lr   = lane & 7;
    const int bk   = lane & 15;
#pragma unroll
    for (int ks = 0; ks < 8; ks++) {
        uint32_t a[2][4];
#pragma unroll
        for (int mt = 0; mt < 2; mt++) {
            int arow = wm * 32 + mt * 16 + (quad & 1) * 8 + lr;
            int acol = ks * 16 + (quad >> 1) * 8;
            ldsm_x4(a[mt], sA32 + (arow * SWH + acol) * 2);
        }
#pragma unroll
        for (int nt = 0; nt < 4; nt++) {
            int brow = ks * 16 + bk;
            int bcol = wn * 32 + nt * 8;
            uint32_t b0, b1;
            ldsm_x2t(b0, b1, sW32 + (brow * SWH + bcol) * 2);
#pragma unroll
            for (int mt = 0; mt < 2; mt++)
                mma_f16(acc[mt][nt], a[mt][0], a[mt][1], a[mt][2], a[mt][3],
                        b0, b1);
        }
    }
}

__device__ __forceinline__ void pack_store(int row, int chunk, int col,
                                           float r0, float r1,
                                           const float* __restrict__ v) {
    if (row >= N_NODES) return;
    __half2* pr = g_pack + (size_t)row * PACK_H2;
    if (chunk == 0) {
#pragma unroll
        for (int a = 0; a < 3; a++) {
            float2 vv = *(const float2*)(v + (size_t)row * H3 + a * H + col);
            pr[128 + a * 64 + (col >> 1)] =
                __floats2half2_rn(r0 * vv.x, r1 * vv.y);
        }
    } else if (chunk == 1) {
        pr[(col - 128) >> 1] = __floats2half2_rn(r0, r1);        // es
    } else {
        pr[64 + ((col - 256) >> 1)] = __floats2half2_rn(r0, r1); // er
    }
}

__global__ __launch_bounds__(256, 3) void embed_kernel(
    const float* __restrict__ s,
    const float* __restrict__ v,
    const float* __restrict__ W1, const float* __restrict__ b1,
    const float* __restrict__ W2, const float* __restrict__ b2)
{
    extern __shared__ __half smem_h[];
    __half* sA = smem_h;                 // BM x SWH
    __half* sW = smem_h + BM * SWH;      // 128 x SWH

    const uint32_t sA32 = (uint32_t)__cvta_generic_to_shared(sA);
    const uint32_t sW32 = (uint32_t)__cvta_generic_to_shared(sW);

    const int t    = threadIdx.x;
    const int r0   = blockIdx.x * BM;
    const int wid  = t >> 5, lane = t & 31;
    const int wm   = wid & 1, wn = wid >> 1;
    const int gid  = lane >> 2, tig = lane & 3;

    // ---- load s tile [64 x 128] (guarded, zero pad), fp16 ----
#pragma unroll
    for (int i = 0; i < 8; i++) {
        int idx4 = t + i * 256;              // 0..2047 float4s
        int row  = idx4 >> 5;
        int c4   = (idx4 & 31) * 4;
        float4 val = make_float4(0.f, 0.f, 0.f, 0.f);
        if (r0 + row < N_NODES)
            val = *(const float4*)(s + (size_t)(r0 + row) * H + c4);
        st_half4(sA, row, c4, val);
    }
    // ---- load W1 [128 x 128], fp16 ----
#pragma unroll
    for (int i = 0; i < 16; i++) {
        int idx4 = t + i * 256;
        int row  = idx4 >> 5;
        int c4   = (idx4 & 31) * 4;
        st_half4(sW, row, c4, *(const float4*)(W1 + (size_t)row * H + c4));
    }
    __syncthreads();

    float acc[2][4][4];
#pragma unroll
    for (int mt = 0; mt < 2; mt++)
#pragma unroll
        for (int nt = 0; nt < 4; nt++)
#pragma unroll
            for (int i = 0; i < 4; i++) acc[mt][nt][i] = 0.f;

    compute_mma16(acc, sA32, sW32, wm, wn, lane);
    __syncthreads();

    // ---- h1 = tanh(acc + b1) back into sA (fp16) ----
#pragma unroll
    for (int mt = 0; mt < 2; mt++) {
        int row = wm * 32 + mt * 16 + gid;
#pragma unroll
        for (int nt = 0; nt < 4; nt++) {
            int col = wn * 32 + nt * 8 + tig * 2;
            float ba = __ldg(b1 + col), bb = __ldg(b1 + col + 1);
            *(half2*)(sA + row * SWH + col) =
                __floats2half2_rn(tanhf(acc[mt][nt][0] + ba),
                                  tanhf(acc[mt][nt][1] + bb));
            *(half2*)(sA + (row + 8) * SWH + col) =
                __floats2half2_rn(tanhf(acc[mt][nt][2] + ba),
                                  tanhf(acc[mt][nt][3] + bb));
        }
    }

    for (int chunk = 0; chunk < 3; chunk++) {
        __syncthreads();
#pragma unroll
        for (int i = 0; i < 16; i++) {
            int idx4 = t + i * 256;
            int row  = idx4 >> 5;
            int c4   = (idx4 & 31) * 4;
            st_half4(sW, row, c4,
                     *(const float4*)(W2 + (size_t)row * H3 + chunk * 128 + c4));
        }
        __syncthreads();

        float acc2[2][4][4];
#pragma unroll
        for (int mt = 0; mt < 2; mt++)
#pragma unroll
            for (int nt = 0; nt < 4; nt++)
#pragma unroll
                for (int i = 0; i < 4; i++) acc2[mt][nt][i] = 0.f;

        compute_mma16(acc2, sA32, sW32, wm, wn, lane);

#pragma unroll
        for (int mt = 0; mt < 2; mt++) {
            int rl = wm * 32 + mt * 16 + gid;
#pragma unroll
            for (int nt = 0; nt < 4; nt++) {
                int col = chunk * 128 + wn * 32 + nt * 8 + tig * 2;
                float ba = __ldg(b2 + col), bb = __ldg(b2 + col + 1);
                int lcol = col - chunk * 128;
                pack_store(r0 + rl, chunk, chunk ? col : lcol,
                           acc2[mt][nt][0] + ba, acc2[mt][nt][1] + bb, v);
                pack_store(r0 + rl + 8, chunk, chunk ? col : lcol,
                           acc2[mt][nt][2] + ba, acc2[mt][nt][3] + bb, v);
            }
        }
    }
}

// ---------------------------------------------------------------------------
// CSR build: histogram -> single-kernel lookback scan -> bucket fill
// ---------------------------------------------------------------------------
__global__ __launch_bounds__(256) void hist_kernel(const int* __restrict__ ei) {
    int i = blockIdx.x * 256 + threadIdx.x;
    if (i < N_EDGES) atomicAdd(&g_state[__ldg(ei + N_EDGES + i)], 1);
}

__global__ __launch_bounds__(SCAN_B) void scan_lb_kernel() {
    __shared__ int tmp[SCAN_B];
    __shared__ int s_prefix;
    const int b = blockIdx.x;
    const int t = threadIdx.x;
    const int idx = b * SCAN_B + t;
    int* states = g_state + 2 * N_NODES;

    int v = (idx < N_NODES) ? g_state[idx] : 0;
    tmp[t] = v;
    __syncthreads();
#pragma unroll
    for (int off = 1; off < SCAN_B; off <<= 1) {
        int u = (t >= off) ? tmp[t - off] : 0;
        __syncthreads();
        tmp[t] += u;
        __syncthreads();
    }
    const int incl = tmp[t];
    const int total = tmp[SCAN_B - 1];

    if (t == 0) {
        if (b == 0) {
            __threadfence();
            atomicExch(&states[0], (total << 2) | 2);   // PREFIX
            s_prefix = 0;
        } else {
            __threadfence();
            atomicExch(&states[b], (total << 2) | 1);   // AGGREGATE
            int run = 0;
            int i = b - 1;
            while (true) {
                int st;
                do { st = atomicAdd(&states[i], 0); } while ((st & 3) == 0);
                run += (st >> 2);
                if ((st & 3) == 2) break;
                --i;
            }
            s_prefix = run;
            __threadfence();
            atomicExch(&states[b], ((run + total) << 2) | 2);
        }
    }
    __syncthreads();

    if (idx < N_NODES) g_start[idx] = s_prefix + incl - v;   // exclusive
    if (idx == 0)      g_start[N_NODES] = N_EDGES;
}

__global__ __launch_bounds__(256) void fill_kernel(
    const int* __restrict__ ei,
    const float* __restrict__ dij,
    const float* __restrict__ dir)
{
    int e = blockIdx.x * 256 + threadIdx.x;
    if (e >= N_EDGES) return;
    int dst = __ldg(ei + N_EDGES + e);
    int pos = g_start[dst] + atomicAdd(&g_state[N_NODES + dst], 1);
    g_bsrc[pos] = __ldg(ei + e);
    g_bdat[pos] = make_float4(__ldg(dij + e), __ldg(dir + 3 * e),
                              __ldg(dir + 3 * e + 1), __ldg(dir + 3 * e + 2));
}

// ---------------------------------------------------------------------------
// Kernel 2: gather + finalize. 128-thread block = 2 nodes x 64 threads.
// 5 packed gathers per edge: es, er, q0[0..2].
// ---------------------------------------------------------------------------
__global__ __launch_bounds__(128) void gather_kernel(
    const float* __restrict__ v,
    const float* __restrict__ s,
    const float* __restrict__ Wd,
    const float* __restrict__ bd,
    float* __restrict__ out)
{
    const int t    = threadIdx.x;
    const int node = blockIdx.x * 2 + (t >> 6);
    const int c    = t & 63;

    const int beg = g_start[node];
    const int end = g_start[node + 1];

    const float2 wv = *(const float2*)(Wd + 2 * c);
    const float2 bv = *(const float2*)(bd + 2 * c);
    const float2 ws = *(const float2*)(Wd + 128 + 2 * c);
    const float2 bs = *(const float2*)(bd + 128 + 2 * c);
    const float2 wr = *(const float2*)(Wd + 256 + 2 * c);
    const float2 br = *(const float2*)(bd + 256 + 2 * c);

    float2 accs = make_float2(0.f, 0.f);
    float2 a0 = accs, a1 = accs, a2 = accs;

#pragma unroll 4
    for (int j = beg; j < end; j++) {
        const int src = __ldg(g_bsrc + j);
        const float4 ed = __ldg(g_bdat + j);    // {d, d0, d1, d2}

        const __half2* pr = g_pack + (size_t)src * PACK_H2;
        const float2 es = __half22float2(__ldg(pr + c));
        const float2 er = __half22float2(__ldg(pr + 64 + c));
        const float2 q0 = __half22float2(__ldg(pr + 128 + c));
        const float2 q1 = __half22float2(__ldg(pr + 192 + c));
        const float2 q2 = __half22float2(__ldg(pr + 256 + c));

        const float gqx = fmaf(ed.x, wv.x, bv.x);
        const float gqy = fmaf(ed.x, wv.y, bv.y);
        const float grx = er.x * fmaf(ed.x, wr.x, br.x);
        const float gry = er.y * fmaf(ed.x, wr.y, br.y);

        accs.x = fmaf(es.x, fmaf(ed.x, ws.x, bs.x), accs.x);
        accs.y = fmaf(es.y, fmaf(ed.x, ws.y, bs.y), accs.y);

        a0.x = fmaf(grx, ed.y, fmaf(gqx, q0.x, a0.x));
        a0.y = fmaf(gry, ed.y, fmaf(gqy, q0.y, a0.y));
        a1.x = fmaf(grx, ed.z, fmaf(gqx, q1.x, a1.x));
        a1.y = fmaf(gry, ed.z, fmaf(gqy, q1.y, a1.y));
        a2.x = fmaf(grx, ed.w, fmaf(gqx, q2.x, a2.x));
        a2.y = fmaf(gry, ed.w, fmaf(gqy, q2.y, a2.y));
    }

    const float inv = 1.0f / fmaxf((float)(end - beg), 1.0f);

    const size_t vb = (size_t)node * H3;
    float2 o;
    float2 x0 = *(const float2*)(v + vb + 2 * c);
    o = make_float2(fmaf(a0.x, inv, x0.x), fmaf(a0.y, inv, x0.y));
    *(float2*)(out + vb + 2 * c) = o;
    float2 x1 = *(const float2*)(v + vb + 128 + 2 * c);
    o = make_float2(fmaf(a1.x, inv, x1.x), fmaf(a1.y, inv, x1.y));
    *(float2*)(out + vb + 128 + 2 * c) = o;
    float2 x2 = *(const float2*)(v + vb + 256 + 2 * c);
    o = make_float2(fmaf(a2.x, inv, x2.x), fmaf(a2.y, inv, x2.y));
    *(float2*)(out + vb + 256 + 2 * c) = o;

    float2 xs = *(const float2*)(s + (size_t)node * H + 2 * c);
    o = make_float2(fmaf(accs.x, inv, xs.x), fmaf(accs.y, inv, xs.y));
    *(float2*)(out + (size_t)N_NODES * H3 + (size_t)node * H + 2 * c) = o;
}

// ---------------------------------------------------------------------------
// Launch (submission order keeps ncu -s 5 on gather):
//   0 memset(sC) 1 hist(sC) 2 scan(sC) 3 fill(sC) 4 embed(s0) 5 gather(s0)
// ---------------------------------------------------------------------------
extern "C" void kernel_launch(void* const* d_in, const int* in_sizes, int n_in,
                              void* d_out, int out_size) {
    const float* v   = (const float*)d_in[0];
    const float* s   = (const float*)d_in[1];
    const int*   ei  = (const int*)  d_in[2];
    const float* dij = (const float*)d_in[3];
    const float* dir = (const float*)d_in[4];
    const float* W1  = (const float*)d_in[5];
    const float* b1  = (const float*)d_in[6];
    const float* W2  = (const float*)d_in[7];
    const float* b2  = (const float*)d_in[8];
    const float* Wd  = (const float*)d_in[9];
    const float* bd  = (const float*)d_in[10];
    float* out = (float*)d_out;

    static cudaStream_t sC = nullptr;
    static cudaEvent_t  eFork = nullptr, eJoinC = nullptr;
    if (sC == nullptr) {
        cudaStreamCreateWithFlags(&sC, cudaStreamNonBlocking);
        cudaEventCreateWithFlags(&eFork,  cudaEventDisableTiming);
        cudaEventCreateWithFlags(&eJoinC, cudaEventDisableTiming);
        cudaFuncSetAttribute(embed_kernel,
                             cudaFuncAttributeMaxDynamicSharedMemorySize,
                             SMEM_EMBED_BYTES);
    }

    void* pstate;
    cudaGetSymbolAddress(&pstate, g_state);

    cudaEventRecord(eFork, 0);
    cudaStreamWaitEvent(sC, eFork, 0);

    // chain C: CSR build
    cudaMemsetAsync(pstate, 0, sizeof(int) * (2 * N_NODES + N_SBLK), sC);
    hist_kernel<<<(N_EDGES + 255) / 256, 256, 0, sC>>>(ei);
    scan_lb_kernel<<<N_SBLK, SCAN_B, 0, sC>>>();
    fill_kernel<<<(N_EDGES + 255) / 256, 256, 0, sC>>>(ei, dij, dir);

    // chain A: embed MLP + pack epilogue
    embed_kernel<<<(N_NODES + BM - 1) / BM, 256, SMEM_EMBED_BYTES>>>(
        s, v, W1, b1, W2, b2);

    cudaEventRecord(eJoinC, sC);
    cudaStreamWaitEvent(0, eJoinC, 0);

    gather_kernel<<<(N_NODES + 1) / 2, 128>>>(v, s, Wd, bd, out);
}